// round 1
// baseline (speedup 1.0000x reference)
#include <cuda_runtime.h>
#include <cstdint>
#include <cstdio>

// ---------------------------------------------------------------------------
// GATv2 3-layer forward.  N=50000, E=500000 (+N self loops), F_IN=128,
// HID=384 (8 heads x 48), OUT=2.  All fp32.
// ---------------------------------------------------------------------------

#define NN_MAX 50000
#define EE_MAX 500000
#define ET_MAX (EE_MAX + NN_MAX)
#define HID 384
#define NHEAD 8
#define CH 48
#define NEG_SLOPE 0.2f

// ------------------------- scratch (device globals) ------------------------
__device__ float    g_xl[NN_MAX * HID];
__device__ float    g_xr[NN_MAX * HID];
__device__ float    g_feat[NN_MAX * HID];
__device__ float    g_outb[NN_MAX * HID];
__device__ float    g_score[ET_MAX * NHEAD];
__device__ float    g_ex[ET_MAX * NHEAD];
__device__ unsigned g_smax[NN_MAX * NHEAD];
__device__ float    g_denom[NN_MAX * NHEAD];
__device__ float    g_xl3[NN_MAX * 2];
__device__ float    g_xr3[NN_MAX * 2];
__device__ float    g_s3[ET_MAX];
__device__ float    g_ex3[ET_MAX];
__device__ unsigned g_smax3[NN_MAX];
__device__ float    g_denom3[NN_MAX];
__device__ float    g_out3[NN_MAX * 2];

// ------------------------------ helpers ------------------------------------
static __device__ __forceinline__ float lrelu(float x) {
    return x > 0.f ? x : NEG_SLOPE * x;
}
// order-preserving float <-> unsigned encoding for atomicMax
static __device__ __forceinline__ unsigned fenc(float f) {
    unsigned u = __float_as_uint(f);
    return (u & 0x80000000u) ? ~u : (u | 0x80000000u);
}
static __device__ __forceinline__ float fdec(unsigned u) {
    return __uint_as_float((u & 0x80000000u) ? (u & 0x7fffffffu) : ~u);
}

// ------------------------------ GEMM ---------------------------------------
// C[M,Nc] = A[M,K] @ B[K,Nc] + bias[Nc].  BM=128 BN=64 BK=16, 256 threads,
// each thread computes 8x4.  Requires K%16==0, Nc%64==0.
__global__ void gemm_bias_kernel(const float* __restrict__ A,
                                 const float* __restrict__ B,
                                 const float* __restrict__ bias,
                                 float* __restrict__ C,
                                 int M, int K, int Nc) {
    __shared__ float As[16][129];   // [k][m], padded
    __shared__ float Bs[16][64];    // [k][n]

    const int tid = threadIdx.x;
    const int rowBase = blockIdx.y * 128;
    const int colBase = blockIdx.x * 64;
    const int trow = (tid / 16) * 8;   // 0..120
    const int tcol = (tid % 16) * 4;   // 0..60

    float acc[8][4];
#pragma unroll
    for (int m = 0; m < 8; m++)
#pragma unroll
        for (int n = 0; n < 4; n++) acc[m][n] = 0.f;

    for (int k0 = 0; k0 < K; k0 += 16) {
        // load A tile 128x16 (8 elems / thread)
#pragma unroll
        for (int i = 0; i < 8; i++) {
            int idx = tid + i * 256;
            int r = idx / 16;
            int c = idx % 16;
            int gr = rowBase + r;
            As[c][r] = (gr < M) ? A[(size_t)gr * K + k0 + c] : 0.f;
        }
        // load B tile 16x64 (4 elems / thread)
#pragma unroll
        for (int i = 0; i < 4; i++) {
            int idx = tid + i * 256;
            int r = idx / 64;
            int c = idx % 64;
            Bs[r][c] = B[(size_t)(k0 + r) * Nc + colBase + c];
        }
        __syncthreads();
#pragma unroll
        for (int kk = 0; kk < 16; kk++) {
            float a[8], b[4];
#pragma unroll
            for (int m = 0; m < 8; m++) a[m] = As[kk][trow + m];
#pragma unroll
            for (int n = 0; n < 4; n++) b[n] = Bs[kk][tcol + n];
#pragma unroll
            for (int m = 0; m < 8; m++)
#pragma unroll
                for (int n = 0; n < 4; n++) acc[m][n] += a[m] * b[n];
        }
        __syncthreads();
    }

#pragma unroll
    for (int m = 0; m < 8; m++) {
        int gr = rowBase + trow + m;
        if (gr >= M) continue;
#pragma unroll
        for (int n = 0; n < 4; n++) {
            int gc = colBase + tcol + n;
            C[(size_t)gr * Nc + gc] = acc[m][n] + bias[gc];
        }
    }
}

// ------------------------- init kernels -------------------------------------
__global__ void init_softmax_kernel(unsigned* smax, float* denom, int n) {
    int i = blockIdx.x * blockDim.x + threadIdx.x;
    if (i < n) { smax[i] = 0u; denom[i] = 0.f; }
}

__global__ void init_out_kernel(float* out, const float* __restrict__ bias, int total) {
    int i = blockIdx.x * blockDim.x + threadIdx.x;
    if (i < total) out[i] = bias[i % HID];
}

__global__ void init_out3_kernel(float* out, const float* __restrict__ bias, int nNodes) {
    int i = blockIdx.x * blockDim.x + threadIdx.x;
    if (i < nNodes * 2) out[i] = bias[i & 1];
}

// -------------------- edge kernels, layers 1/2 ------------------------------
// one thread per (edge, head)
__global__ void edge_score_kernel(const float* __restrict__ xl,
                                  const float* __restrict__ xr,
                                  const float* __restrict__ att,
                                  const int* __restrict__ src,
                                  const int* __restrict__ dst,
                                  float* __restrict__ score,
                                  unsigned* __restrict__ smax,
                                  int Etot, int E) {
    int t = blockIdx.x * blockDim.x + threadIdx.x;
    if (t >= Etot * NHEAD) return;
    int e = t >> 3;
    int h = t & 7;
    int s, d;
    if (e < E) { s = src[e]; d = dst[e]; } else { s = d = e - E; }

    const float4* pl = reinterpret_cast<const float4*>(xl + (size_t)s * HID + h * CH);
    const float4* pr = reinterpret_cast<const float4*>(xr + (size_t)d * HID + h * CH);
    const float4* pa = reinterpret_cast<const float4*>(att + h * CH);
    float acc = 0.f;
#pragma unroll
    for (int i = 0; i < 12; i++) {
        float4 a = pl[i];
        float4 b = pr[i];
        float4 w = pa[i];
        acc += lrelu(a.x + b.x) * w.x;
        acc += lrelu(a.y + b.y) * w.y;
        acc += lrelu(a.z + b.z) * w.z;
        acc += lrelu(a.w + b.w) * w.w;
    }
    score[t] = acc;
    atomicMax(&smax[d * NHEAD + h], fenc(acc));
}

__global__ void edge_exp_kernel(const float* __restrict__ score,
                                const unsigned* __restrict__ smax,
                                const int* __restrict__ dst,
                                float* __restrict__ ex,
                                float* __restrict__ denom,
                                int Etot, int E) {
    int t = blockIdx.x * blockDim.x + threadIdx.x;
    if (t >= Etot * NHEAD) return;
    int e = t >> 3;
    int h = t & 7;
    int d = (e < E) ? dst[e] : (e - E);
    float v = expf(score[t] - fdec(smax[d * NHEAD + h]));
    ex[t] = v;
    atomicAdd(&denom[d * NHEAD + h], v);
}

__global__ void edge_agg_kernel(const float* __restrict__ xl,
                                const float* __restrict__ ex,
                                const float* __restrict__ denom,
                                const int* __restrict__ src,
                                const int* __restrict__ dst,
                                float* __restrict__ out,
                                int Etot, int E) {
    int t = blockIdx.x * blockDim.x + threadIdx.x;
    if (t >= Etot * NHEAD) return;
    int e = t >> 3;
    int h = t & 7;
    int s, d;
    if (e < E) { s = src[e]; d = dst[e]; } else { s = d = e - E; }
    float a = ex[t] / (denom[d * NHEAD + h] + 1e-16f);
    const float4* pl = reinterpret_cast<const float4*>(xl + (size_t)s * HID + h * CH);
    float* po = out + (size_t)d * HID + h * CH;
#pragma unroll
    for (int i = 0; i < 12; i++) {
        float4 v = pl[i];
        atomicAdd(po + 4 * i + 0, v.x * a);
        atomicAdd(po + 4 * i + 1, v.y * a);
        atomicAdd(po + 4 * i + 2, v.z * a);
        atomicAdd(po + 4 * i + 3, v.w * a);
    }
}

__global__ void elu_kernel(const float* __restrict__ in, float* __restrict__ out, int n) {
    int i = blockIdx.x * blockDim.x + threadIdx.x;
    if (i < n) {
        float x = in[i];
        out[i] = x > 0.f ? x : expm1f(x);
    }
}

// ------------------------- layer 3 kernels ----------------------------------
// warp per node: compute xl3[n,0:2], xr3[n,0:2]
__global__ void l3_transform_kernel(const float* __restrict__ h,
                                    const float* __restrict__ Wl, const float* __restrict__ bl,
                                    const float* __restrict__ Wr, const float* __restrict__ br,
                                    float* __restrict__ xl3, float* __restrict__ xr3,
                                    int nNodes) {
    int warp = (blockIdx.x * blockDim.x + threadIdx.x) >> 5;
    int lane = threadIdx.x & 31;
    if (warp >= nNodes) return;
    const float* row = h + (size_t)warp * HID;
    float a0 = 0.f, a1 = 0.f, b0 = 0.f, b1 = 0.f;
#pragma unroll
    for (int k = lane; k < HID; k += 32) {
        float v = row[k];
        a0 += v * Wl[k * 2];
        a1 += v * Wl[k * 2 + 1];
        b0 += v * Wr[k * 2];
        b1 += v * Wr[k * 2 + 1];
    }
#pragma unroll
    for (int o = 16; o; o >>= 1) {
        a0 += __shfl_down_sync(0xffffffffu, a0, o);
        a1 += __shfl_down_sync(0xffffffffu, a1, o);
        b0 += __shfl_down_sync(0xffffffffu, b0, o);
        b1 += __shfl_down_sync(0xffffffffu, b1, o);
    }
    if (lane == 0) {
        xl3[warp * 2]     = a0 + bl[0];
        xl3[warp * 2 + 1] = a1 + bl[1];
        xr3[warp * 2]     = b0 + br[0];
        xr3[warp * 2 + 1] = b1 + br[1];
    }
}

__global__ void l3_score_kernel(const float* __restrict__ xl3,
                                const float* __restrict__ xr3,
                                const float* __restrict__ att,
                                const int* __restrict__ src,
                                const int* __restrict__ dst,
                                float* __restrict__ s3,
                                unsigned* __restrict__ smax3,
                                int Etot, int E) {
    int e = blockIdx.x * blockDim.x + threadIdx.x;
    if (e >= Etot) return;
    int s, d;
    if (e < E) { s = src[e]; d = dst[e]; } else { s = d = e - E; }
    float m0 = xl3[2 * s]     + xr3[2 * d];
    float m1 = xl3[2 * s + 1] + xr3[2 * d + 1];
    float sc = lrelu(m0) * att[0] + lrelu(m1) * att[1];
    s3[e] = sc;
    atomicMax(&smax3[d], fenc(sc));
}

__global__ void l3_exp_kernel(const float* __restrict__ s3,
                              const unsigned* __restrict__ smax3,
                              const int* __restrict__ dst,
                              float* __restrict__ ex3,
                              float* __restrict__ denom3,
                              int Etot, int E) {
    int e = blockIdx.x * blockDim.x + threadIdx.x;
    if (e >= Etot) return;
    int d = (e < E) ? dst[e] : (e - E);
    float v = expf(s3[e] - fdec(smax3[d]));
    ex3[e] = v;
    atomicAdd(&denom3[d], v);
}

__global__ void l3_agg_kernel(const float* __restrict__ xl3,
                              const float* __restrict__ ex3,
                              const float* __restrict__ denom3,
                              const int* __restrict__ src,
                              const int* __restrict__ dst,
                              float* __restrict__ out3,
                              int Etot, int E) {
    int e = blockIdx.x * blockDim.x + threadIdx.x;
    if (e >= Etot) return;
    int s, d;
    if (e < E) { s = src[e]; d = dst[e]; } else { s = d = e - E; }
    float a = ex3[e] / (denom3[d] + 1e-16f);
    atomicAdd(&out3[2 * d],     xl3[2 * s]     * a);
    atomicAdd(&out3[2 * d + 1], xl3[2 * s + 1] * a);
}

__global__ void logsoftmax_kernel(const float* __restrict__ out3,
                                  float* __restrict__ y, int nNodes) {
    int n = blockIdx.x * blockDim.x + threadIdx.x;
    if (n >= nNodes) return;
    float z0 = out3[2 * n];
    float z1 = out3[2 * n + 1];
    float m = fmaxf(z0, z1);
    float l = m + logf(expf(z0 - m) + expf(z1 - m));
    y[2 * n] = z0 - l;
    y[2 * n + 1] = z1 - l;
}

// ------------------------------ host ---------------------------------------
extern "C" void kernel_launch(void* const* d_in, const int* in_sizes, int n_in,
                              void* d_out, int out_size) {
    const float* x     = (const float*)d_in[0];
    const int*   eidx  = (const int*)d_in[1];
    const float* Wl1   = (const float*)d_in[2];
    const float* bl1   = (const float*)d_in[3];
    const float* Wr1   = (const float*)d_in[4];
    const float* br1   = (const float*)d_in[5];
    const float* att1  = (const float*)d_in[6];
    const float* bias1 = (const float*)d_in[7];
    const float* Wl2   = (const float*)d_in[8];
    const float* bl2   = (const float*)d_in[9];
    const float* Wr2   = (const float*)d_in[10];
    const float* br2   = (const float*)d_in[11];
    const float* att2  = (const float*)d_in[12];
    const float* bias2 = (const float*)d_in[13];
    const float* Wl3   = (const float*)d_in[14];
    const float* bl3   = (const float*)d_in[15];
    const float* Wr3   = (const float*)d_in[16];
    const float* br3   = (const float*)d_in[17];
    const float* att3  = (const float*)d_in[18];
    const float* bias3 = (const float*)d_in[19];

    const int nN = in_sizes[0] / 128;      // 50000
    const int nE = in_sizes[1] / 2;        // 500000
    const int nEt = nE + nN;               // 550000
    const int* srcArr = eidx;
    const int* dstArr = eidx + nE;

    float*    xl;     cudaGetSymbolAddress((void**)&xl, g_xl);
    float*    xr;     cudaGetSymbolAddress((void**)&xr, g_xr);
    float*    feat;   cudaGetSymbolAddress((void**)&feat, g_feat);
    float*    outb;   cudaGetSymbolAddress((void**)&outb, g_outb);
    float*    score;  cudaGetSymbolAddress((void**)&score, g_score);
    float*    ex;     cudaGetSymbolAddress((void**)&ex, g_ex);
    unsigned* smax;   cudaGetSymbolAddress((void**)&smax, g_smax);
    float*    denom;  cudaGetSymbolAddress((void**)&denom, g_denom);
    float*    xl3;    cudaGetSymbolAddress((void**)&xl3, g_xl3);
    float*    xr3;    cudaGetSymbolAddress((void**)&xr3, g_xr3);
    float*    s3;     cudaGetSymbolAddress((void**)&s3, g_s3);
    float*    ex3;    cudaGetSymbolAddress((void**)&ex3, g_ex3);
    unsigned* smax3;  cudaGetSymbolAddress((void**)&smax3, g_smax3);
    float*    denom3; cudaGetSymbolAddress((void**)&denom3, g_denom3);
    float*    out3;   cudaGetSymbolAddress((void**)&out3, g_out3);

    const dim3 gemmBlk(256);
    const dim3 gemmGrd1(HID / 64, (nN + 127) / 128);
    const int EB = 256;
    const int ehThreads = nEt * NHEAD;
    const int ehGrid = (ehThreads + EB - 1) / EB;
    const int eGrid = (nEt + EB - 1) / EB;
    const int nhGrid = (nN * NHEAD + EB - 1) / EB;
    const int featGrid = (nN * HID + EB - 1) / EB;

    // ------------------ layer 1 ------------------
    gemm_bias_kernel<<<gemmGrd1, gemmBlk>>>(x, Wl1, bl1, xl, nN, 128, HID);
    gemm_bias_kernel<<<gemmGrd1, gemmBlk>>>(x, Wr1, br1, xr, nN, 128, HID);
    init_softmax_kernel<<<nhGrid, EB>>>(smax, denom, nN * NHEAD);
    edge_score_kernel<<<ehGrid, EB>>>(xl, xr, att1, srcArr, dstArr, score, smax, nEt, nE);
    edge_exp_kernel<<<ehGrid, EB>>>(score, smax, dstArr, ex, denom, nEt, nE);
    init_out_kernel<<<featGrid, EB>>>(outb, bias1, nN * HID);
    edge_agg_kernel<<<ehGrid, EB>>>(xl, ex, denom, srcArr, dstArr, outb, nEt, nE);
    elu_kernel<<<featGrid, EB>>>(outb, feat, nN * HID);

    // ------------------ layer 2 ------------------
    gemm_bias_kernel<<<gemmGrd1, gemmBlk>>>(feat, Wl2, bl2, xl, nN, HID, HID);
    gemm_bias_kernel<<<gemmGrd1, gemmBlk>>>(feat, Wr2, br2, xr, nN, HID, HID);
    init_softmax_kernel<<<nhGrid, EB>>>(smax, denom, nN * NHEAD);
    edge_score_kernel<<<ehGrid, EB>>>(xl, xr, att2, srcArr, dstArr, score, smax, nEt, nE);
    edge_exp_kernel<<<ehGrid, EB>>>(score, smax, dstArr, ex, denom, nEt, nE);
    init_out_kernel<<<featGrid, EB>>>(outb, bias2, nN * HID);
    edge_agg_kernel<<<ehGrid, EB>>>(xl, ex, denom, srcArr, dstArr, outb, nEt, nE);
    elu_kernel<<<featGrid, EB>>>(outb, feat, nN * HID);

    // ------------------ layer 3 ------------------
    l3_transform_kernel<<<(nN * 32 + EB - 1) / EB, EB>>>(feat, Wl3, bl3, Wr3, br3,
                                                         xl3, xr3, nN);
    init_softmax_kernel<<<(nN + EB - 1) / EB, EB>>>(smax3, denom3, nN);
    l3_score_kernel<<<eGrid, EB>>>(xl3, xr3, att3, srcArr, dstArr, s3, smax3, nEt, nE);
    l3_exp_kernel<<<eGrid, EB>>>(s3, smax3, dstArr, ex3, denom3, nEt, nE);
    init_out3_kernel<<<(nN * 2 + EB - 1) / EB, EB>>>(out3, bias3, nN);
    l3_agg_kernel<<<eGrid, EB>>>(xl3, ex3, denom3, srcArr, dstArr, out3, nEt, nE);
    logsoftmax_kernel<<<(nN + EB - 1) / EB, EB>>>(out3, (float*)d_out, nN);
}

// round 2
// speedup vs baseline: 2.7295x; 2.7295x over previous
#include <cuda_runtime.h>
#include <cstdint>

// ---------------------------------------------------------------------------
// GATv2 3-layer forward, CSR-fused version.
// N=50000, E=500000 (+N self loops), F_IN=128, HID=384 (8 heads x 48), OUT=2.
// ---------------------------------------------------------------------------

#define NN_MAX 50000
#define EE_MAX 500000
#define ET_MAX (EE_MAX + NN_MAX)
#define HID 384
#define NHEAD 8
#define CH 48
#define NEG 0.2f

// ------------------------- scratch (device globals) ------------------------
__device__ float g_xl[NN_MAX * HID];
__device__ float g_xr[NN_MAX * HID];
__device__ float g_feat[NN_MAX * HID];
__device__ float g_escore[(size_t)ET_MAX * NHEAD];
__device__ int   g_deg[NN_MAX];
__device__ int   g_rowptr[NN_MAX + 1];
__device__ int   g_pos[NN_MAX];
__device__ int   g_eperm[ET_MAX];
__device__ int   g_bsum[256];
__device__ float g_xl3[NN_MAX * 2];
__device__ float g_xr3[NN_MAX * 2];

// ------------------------------ CSR build -----------------------------------
__global__ void deg_init_kernel(int* deg, int nN) {
    int i = blockIdx.x * blockDim.x + threadIdx.x;
    if (i < nN) deg[i] = 1;   // self loop
}

__global__ void deg_hist_kernel(const int* __restrict__ dst, int* deg, int E) {
    int e = blockIdx.x * blockDim.x + threadIdx.x;
    if (e < E) atomicAdd(&deg[dst[e]], 1);
}

__global__ void scan_block_sums(const int* __restrict__ deg, int* bsum, int nN) {
    __shared__ int sm[256];
    int i = blockIdx.x * 256 + threadIdx.x;
    sm[threadIdx.x] = (i < nN) ? deg[i] : 0;
    __syncthreads();
    for (int o = 128; o; o >>= 1) {
        if (threadIdx.x < o) sm[threadIdx.x] += sm[threadIdx.x + o];
        __syncthreads();
    }
    if (threadIdx.x == 0) bsum[blockIdx.x] = sm[0];
}

__global__ void scan_bsum_kernel(int* bsum, int nb) {
    __shared__ int sm[256];
    int t = threadIdx.x;
    int v = (t < nb) ? bsum[t] : 0;
    sm[t] = v;
    __syncthreads();
    for (int o = 1; o < 256; o <<= 1) {
        int add = (t >= o) ? sm[t - o] : 0;
        __syncthreads();
        sm[t] += add;
        __syncthreads();
    }
    if (t < nb) bsum[t] = sm[t] - v;   // exclusive
}

__global__ void scan_final_kernel(const int* __restrict__ deg, const int* __restrict__ bsum,
                                  int* rowptr, int* pos, int nN, int nEt) {
    __shared__ int sm[256];
    int t = threadIdx.x;
    int i = blockIdx.x * 256 + t;
    int v = (i < nN) ? deg[i] : 0;
    sm[t] = v;
    __syncthreads();
    for (int o = 1; o < 256; o <<= 1) {
        int add = (t >= o) ? sm[t - o] : 0;
        __syncthreads();
        sm[t] += add;
        __syncthreads();
    }
    if (i < nN) {
        int ex = sm[t] - v + bsum[blockIdx.x];
        rowptr[i] = ex;
        pos[i] = ex;
    }
    if (i == 0) rowptr[nN] = nEt;
}

__global__ void scatter_kernel(const int* __restrict__ src, const int* __restrict__ dst,
                               int* pos, int* eperm, int E, int nN) {
    int t = blockIdx.x * blockDim.x + threadIdx.x;
    if (t >= E + nN) return;
    int s, d;
    if (t < E) { s = src[t]; d = dst[t]; } else { s = d = t - E; }
    int p = atomicAdd(&pos[d], 1);
    eperm[p] = s;
}

// ------------------------------ GEMM ----------------------------------------
// C[M,Nc] = A[M,K] @ B[K,Nc] + bias.  128x128 tile, BK=16, 256 thr, 8x8/thread.
__global__ __launch_bounds__(256) void gemm_bias_kernel(
    const float* __restrict__ A, const float* __restrict__ B,
    const float* __restrict__ bias, float* __restrict__ C,
    int M, int K, int Nc) {
    __shared__ float As[16][132];
    __shared__ float Bs[16][128];

    const int tid = threadIdx.x;
    const int rowBase = blockIdx.y * 128;
    const int colBase = blockIdx.x * 128;
    const int tx = tid & 15, ty = tid >> 4;

    float acc[8][8];
#pragma unroll
    for (int i = 0; i < 8; i++)
#pragma unroll
        for (int j = 0; j < 8; j++) acc[i][j] = 0.f;

    float4 aR[2], bR[2];
    // index decode for loads
    int amrow[2], akq[2], bk[2], bn[2];
#pragma unroll
    for (int j = 0; j < 2; j++) {
        int ia = tid * 2 + j;
        amrow[j] = ia >> 2;
        akq[j] = (ia & 3) << 2;
        bk[j] = ia >> 5;
        bn[j] = (ia & 31) << 2;
    }

    // prologue: load tile k0=0
#pragma unroll
    for (int j = 0; j < 2; j++) {
        int gr = rowBase + amrow[j];
        aR[j] = (gr < M) ? *(const float4*)&A[(size_t)gr * K + akq[j]]
                         : make_float4(0.f, 0.f, 0.f, 0.f);
        bR[j] = *(const float4*)&B[(size_t)bk[j] * Nc + colBase + bn[j]];
    }
#pragma unroll
    for (int j = 0; j < 2; j++) {
        As[akq[j] + 0][amrow[j]] = aR[j].x;
        As[akq[j] + 1][amrow[j]] = aR[j].y;
        As[akq[j] + 2][amrow[j]] = aR[j].z;
        As[akq[j] + 3][amrow[j]] = aR[j].w;
        *(float4*)&Bs[bk[j]][bn[j]] = bR[j];
    }
    __syncthreads();

    for (int k0 = 16;; k0 += 16) {
        bool more = (k0 < K);
        if (more) {
#pragma unroll
            for (int j = 0; j < 2; j++) {
                int gr = rowBase + amrow[j];
                aR[j] = (gr < M) ? *(const float4*)&A[(size_t)gr * K + k0 + akq[j]]
                                 : make_float4(0.f, 0.f, 0.f, 0.f);
                bR[j] = *(const float4*)&B[(size_t)(k0 + bk[j]) * Nc + colBase + bn[j]];
            }
        }
#pragma unroll
        for (int kk = 0; kk < 16; kk++) {
            float4 a0 = *(const float4*)&As[kk][ty * 8];
            float4 a1 = *(const float4*)&As[kk][ty * 8 + 4];
            float4 b0 = *(const float4*)&Bs[kk][tx * 8];
            float4 b1 = *(const float4*)&Bs[kk][tx * 8 + 4];
            float am[8] = {a0.x, a0.y, a0.z, a0.w, a1.x, a1.y, a1.z, a1.w};
            float bn8[8] = {b0.x, b0.y, b0.z, b0.w, b1.x, b1.y, b1.z, b1.w};
#pragma unroll
            for (int i = 0; i < 8; i++)
#pragma unroll
                for (int j = 0; j < 8; j++) acc[i][j] += am[i] * bn8[j];
        }
        if (!more) break;
        __syncthreads();
#pragma unroll
        for (int j = 0; j < 2; j++) {
            As[akq[j] + 0][amrow[j]] = aR[j].x;
            As[akq[j] + 1][amrow[j]] = aR[j].y;
            As[akq[j] + 2][amrow[j]] = aR[j].z;
            As[akq[j] + 3][amrow[j]] = aR[j].w;
            *(float4*)&Bs[bk[j]][bn[j]] = bR[j];
        }
        __syncthreads();
    }

#pragma unroll
    for (int i = 0; i < 8; i++) {
        int gr = rowBase + ty * 8 + i;
        if (gr >= M) continue;
#pragma unroll
        for (int j = 0; j < 8; j += 4) {
            int gc = colBase + tx * 8 + j;
            float4 o;
            o.x = acc[i][j + 0] + bias[gc + 0];
            o.y = acc[i][j + 1] + bias[gc + 1];
            o.z = acc[i][j + 2] + bias[gc + 2];
            o.w = acc[i][j + 3] + bias[gc + 3];
            *(float4*)&C[(size_t)gr * Nc + gc] = o;
        }
    }
}

// --------------------- fused GATv2 layer (layers 1 & 2) ---------------------
// One warp per destination node.  Lane L: head h=L/4, sub=L%4, handles float4
// indices f0+4c of the 96-float4 row where f0 = 12*h + sub, c = 0..2.
__global__ __launch_bounds__(256) void gat_fused_kernel(
    const float* __restrict__ xl, const float* __restrict__ xr,
    const float* __restrict__ att, const float* __restrict__ bias,
    const int* __restrict__ rowptr, const int* __restrict__ eperm,
    float* __restrict__ escore, float* __restrict__ outFeat, int nN) {
    int warp = (blockIdx.x * blockDim.x + threadIdx.x) >> 5;
    if (warp >= nN) return;
    const int L = threadIdx.x & 31;
    const int h = L >> 2;
    const int sub = L & 3;
    const int f0 = 12 * h + sub;

    const float4* xl4 = (const float4*)xl;
    const float4* xr4 = (const float4*)xr;
    const float4* att4 = (const float4*)att;
    const float4* bias4 = (const float4*)bias;

    float4 rxr[3], ratt[3];
#pragma unroll
    for (int c = 0; c < 3; c++) {
        rxr[c] = xr4[(size_t)warp * 96 + f0 + 4 * c];
        ratt[c] = att4[f0 + 4 * c];
    }

    const int s0 = rowptr[warp];
    const int s1 = rowptr[warp + 1];

    // pass 1: scores + per-head max
    float mx = -3.402823466e38f;
    for (int e = s0; e < s1; e++) {
        int s = eperm[e];
        float p = 0.f;
#pragma unroll
        for (int c = 0; c < 3; c++) {
            float4 a = xl4[(size_t)s * 96 + f0 + 4 * c];
            float4 r = rxr[c], w = ratt[c];
            float v;
            v = a.x + r.x; p += (v > 0.f ? v : NEG * v) * w.x;
            v = a.y + r.y; p += (v > 0.f ? v : NEG * v) * w.y;
            v = a.z + r.z; p += (v > 0.f ? v : NEG * v) * w.z;
            v = a.w + r.w; p += (v > 0.f ? v : NEG * v) * w.w;
        }
        p += __shfl_down_sync(0xffffffffu, p, 2);
        p += __shfl_down_sync(0xffffffffu, p, 1);
        if (sub == 0) {
            escore[(size_t)e * 8 + h] = p;
            mx = fmaxf(mx, p);
        }
    }

    // pass 2: exp + denom (only lead lane of each quad)
    float inv = 0.f;
    if (sub == 0) {
        float den = 0.f;
        for (int e = s0; e < s1; e++) {
            float v = expf(escore[(size_t)e * 8 + h] - mx);
            escore[(size_t)e * 8 + h] = v;
            den += v;
        }
        inv = 1.f / (den + 1e-16f);
    }

    // pass 3: weighted aggregation
    float4 acc[3];
#pragma unroll
    for (int c = 0; c < 3; c++) acc[c] = make_float4(0.f, 0.f, 0.f, 0.f);

    for (int e = s0; e < s1; e++) {
        int s = eperm[e];
        float av = (sub == 0) ? escore[(size_t)e * 8 + h] * inv : 0.f;
        float alpha = __shfl_sync(0xffffffffu, av, L & ~3);
#pragma unroll
        for (int c = 0; c < 3; c++) {
            float4 a = xl4[(size_t)s * 96 + f0 + 4 * c];
            acc[c].x += alpha * a.x;
            acc[c].y += alpha * a.y;
            acc[c].z += alpha * a.z;
            acc[c].w += alpha * a.w;
        }
    }

    // bias + ELU + write
#pragma unroll
    for (int c = 0; c < 3; c++) {
        float4 b = bias4[f0 + 4 * c];
        float4 o;
        o.x = acc[c].x + b.x; o.x = o.x > 0.f ? o.x : expm1f(o.x);
        o.y = acc[c].y + b.y; o.y = o.y > 0.f ? o.y : expm1f(o.y);
        o.z = acc[c].z + b.z; o.z = o.z > 0.f ? o.z : expm1f(o.z);
        o.w = acc[c].w + b.w; o.w = o.w > 0.f ? o.w : expm1f(o.w);
        ((float4*)outFeat)[(size_t)warp * 96 + f0 + 4 * c] = o;
    }
}

// ------------------------- layer 3 ------------------------------------------
__global__ void l3_transform_kernel(const float* __restrict__ hfeat,
                                    const float* __restrict__ Wl, const float* __restrict__ bl,
                                    const float* __restrict__ Wr, const float* __restrict__ br,
                                    float* __restrict__ xl3, float* __restrict__ xr3,
                                    int nN) {
    int warp = (blockIdx.x * blockDim.x + threadIdx.x) >> 5;
    int lane = threadIdx.x & 31;
    if (warp >= nN) return;
    const float* row = hfeat + (size_t)warp * HID;
    float a0 = 0.f, a1 = 0.f, b0 = 0.f, b1 = 0.f;
#pragma unroll
    for (int k = lane; k < HID; k += 32) {
        float v = row[k];
        a0 += v * Wl[k * 2];
        a1 += v * Wl[k * 2 + 1];
        b0 += v * Wr[k * 2];
        b1 += v * Wr[k * 2 + 1];
    }
#pragma unroll
    for (int o = 16; o; o >>= 1) {
        a0 += __shfl_down_sync(0xffffffffu, a0, o);
        a1 += __shfl_down_sync(0xffffffffu, a1, o);
        b0 += __shfl_down_sync(0xffffffffu, b0, o);
        b1 += __shfl_down_sync(0xffffffffu, b1, o);
    }
    if (lane == 0) {
        xl3[warp * 2] = a0 + bl[0];
        xl3[warp * 2 + 1] = a1 + bl[1];
        xr3[warp * 2] = b0 + br[0];
        xr3[warp * 2 + 1] = b1 + br[1];
    }
}

// warp per node; edges parallel across lanes; scores recomputed in pass 2
__global__ void l3_fused_kernel(const float* __restrict__ xl3, const float* __restrict__ xr3,
                                const float* __restrict__ att3, const float* __restrict__ bias3,
                                const int* __restrict__ rowptr, const int* __restrict__ eperm,
                                float* __restrict__ out, int nN) {
    int warp = (blockIdx.x * blockDim.x + threadIdx.x) >> 5;
    if (warp >= nN) return;
    const int L = threadIdx.x & 31;
    const float xr0 = xr3[2 * warp], xr1 = xr3[2 * warp + 1];
    const float a0 = att3[0], a1 = att3[1];
    const int s0 = rowptr[warp], s1 = rowptr[warp + 1];

    float mx = -3.402823466e38f;
    for (int e = s0 + L; e < s1; e += 32) {
        int s = eperm[e];
        float m0 = xl3[2 * s] + xr0;
        float m1 = xl3[2 * s + 1] + xr1;
        float sc = (m0 > 0.f ? m0 : NEG * m0) * a0 + (m1 > 0.f ? m1 : NEG * m1) * a1;
        mx = fmaxf(mx, sc);
    }
#pragma unroll
    for (int o = 16; o; o >>= 1) mx = fmaxf(mx, __shfl_xor_sync(0xffffffffu, mx, o));

    float den = 0.f, n0 = 0.f, n1 = 0.f;
    for (int e = s0 + L; e < s1; e += 32) {
        int s = eperm[e];
        float x0 = xl3[2 * s], x1 = xl3[2 * s + 1];
        float m0 = x0 + xr0, m1 = x1 + xr1;
        float sc = (m0 > 0.f ? m0 : NEG * m0) * a0 + (m1 > 0.f ? m1 : NEG * m1) * a1;
        float v = expf(sc - mx);
        den += v;
        n0 += v * x0;
        n1 += v * x1;
    }
#pragma unroll
    for (int o = 16; o; o >>= 1) {
        den += __shfl_xor_sync(0xffffffffu, den, o);
        n0 += __shfl_xor_sync(0xffffffffu, n0, o);
        n1 += __shfl_xor_sync(0xffffffffu, n1, o);
    }
    if (L == 0) {
        float id = 1.f / (den + 1e-16f);
        float z0 = n0 * id + bias3[0];
        float z1 = n1 * id + bias3[1];
        float m = fmaxf(z0, z1);
        float l = m + logf(expf(z0 - m) + expf(z1 - m));
        out[2 * warp] = z0 - l;
        out[2 * warp + 1] = z1 - l;
    }
}

// ------------------------------ host ----------------------------------------
extern "C" void kernel_launch(void* const* d_in, const int* in_sizes, int n_in,
                              void* d_out, int out_size) {
    const float* x     = (const float*)d_in[0];
    const int*   eidx  = (const int*)d_in[1];
    const float* Wl1   = (const float*)d_in[2];
    const float* bl1   = (const float*)d_in[3];
    const float* Wr1   = (const float*)d_in[4];
    const float* br1   = (const float*)d_in[5];
    const float* att1  = (const float*)d_in[6];
    const float* bias1 = (const float*)d_in[7];
    const float* Wl2   = (const float*)d_in[8];
    const float* bl2   = (const float*)d_in[9];
    const float* Wr2   = (const float*)d_in[10];
    const float* br2   = (const float*)d_in[11];
    const float* att2  = (const float*)d_in[12];
    const float* bias2 = (const float*)d_in[13];
    const float* Wl3   = (const float*)d_in[14];
    const float* bl3   = (const float*)d_in[15];
    const float* Wr3   = (const float*)d_in[16];
    const float* br3   = (const float*)d_in[17];
    const float* att3  = (const float*)d_in[18];
    const float* bias3 = (const float*)d_in[19];

    const int nN = in_sizes[0] / 128;
    const int nE = in_sizes[1] / 2;
    const int nEt = nE + nN;
    const int* srcArr = eidx;
    const int* dstArr = eidx + nE;

    float* xl;     cudaGetSymbolAddress((void**)&xl, g_xl);
    float* xr;     cudaGetSymbolAddress((void**)&xr, g_xr);
    float* feat;   cudaGetSymbolAddress((void**)&feat, g_feat);
    float* escore; cudaGetSymbolAddress((void**)&escore, g_escore);
    int* deg;      cudaGetSymbolAddress((void**)&deg, g_deg);
    int* rowptr;   cudaGetSymbolAddress((void**)&rowptr, g_rowptr);
    int* pos;      cudaGetSymbolAddress((void**)&pos, g_pos);
    int* eperm;    cudaGetSymbolAddress((void**)&eperm, g_eperm);
    int* bsum;     cudaGetSymbolAddress((void**)&bsum, g_bsum);
    float* xl3;    cudaGetSymbolAddress((void**)&xl3, g_xl3);
    float* xr3;    cudaGetSymbolAddress((void**)&xr3, g_xr3);

    const int nb = (nN + 255) / 256;   // 196 scan blocks

    // ----- CSR build (reused by all 3 layers) -----
    deg_init_kernel<<<nb, 256>>>(deg, nN);
    deg_hist_kernel<<<(nE + 255) / 256, 256>>>(dstArr, deg, nE);
    scan_block_sums<<<nb, 256>>>(deg, bsum, nN);
    scan_bsum_kernel<<<1, 256>>>(bsum, nb);
    scan_final_kernel<<<nb, 256>>>(deg, bsum, rowptr, pos, nN, nEt);
    scatter_kernel<<<(nEt + 255) / 256, 256>>>(srcArr, dstArr, pos, eperm, nE, nN);

    const dim3 gemmGrd(HID / 128, (nN + 127) / 128);
    const int fusedGrid = (nN + 7) / 8;   // 8 warps per block

    // ----- layer 1 -----
    gemm_bias_kernel<<<gemmGrd, 256>>>(x, Wl1, bl1, xl, nN, 128, HID);
    gemm_bias_kernel<<<gemmGrd, 256>>>(x, Wr1, br1, xr, nN, 128, HID);
    gat_fused_kernel<<<fusedGrid, 256>>>(xl, xr, att1, bias1, rowptr, eperm,
                                         escore, feat, nN);

    // ----- layer 2 -----
    gemm_bias_kernel<<<gemmGrd, 256>>>(feat, Wl2, bl2, xl, nN, HID, HID);
    gemm_bias_kernel<<<gemmGrd, 256>>>(feat, Wr2, br2, xr, nN, HID, HID);
    gat_fused_kernel<<<fusedGrid, 256>>>(xl, xr, att2, bias2, rowptr, eperm,
                                         escore, feat, nN);

    // ----- layer 3 -----
    l3_transform_kernel<<<(nN * 32 + 255) / 256, 256>>>(feat, Wl3, bl3, Wr3, br3,
                                                        xl3, xr3, nN);
    l3_fused_kernel<<<fusedGrid, 256>>>(xl3, xr3, att3, bias3, rowptr, eperm,
                                        (float*)d_out, nN);
}

// round 3
// speedup vs baseline: 3.6916x; 1.3525x over previous
#include <cuda_runtime.h>
#include <cstdint>
#include <cfloat>

// ---------------------------------------------------------------------------
// GATv2 3-layer forward.  CSR + online-softmax fused edges + TF32-split MMA.
// N=50000, E=500000 (+N self loops), F_IN=128, HID=384 (8 heads x 48), OUT=2.
// ---------------------------------------------------------------------------

#define NN_MAX 50000
#define EE_MAX 500000
#define ET_MAX (EE_MAX + NN_MAX)
#define HID 384
#define NHEAD 8
#define CH 48
#define NEG 0.2f

// ------------------------- scratch (device globals) ------------------------
__device__ float g_xl[NN_MAX * HID];
__device__ float g_xr[NN_MAX * HID];
__device__ float g_feat[NN_MAX * HID];
__device__ int   g_deg[NN_MAX];
__device__ int   g_rowptr[NN_MAX + 1];
__device__ int   g_pos[NN_MAX];
__device__ int   g_eperm[ET_MAX];
__device__ int   g_bsum[256];
__device__ float g_xl3[NN_MAX * 2];
__device__ float g_xr3[NN_MAX * 2];

// ------------------------------ CSR build -----------------------------------
__global__ void deg_init_kernel(int* deg, int nN) {
    int i = blockIdx.x * blockDim.x + threadIdx.x;
    if (i < nN) deg[i] = 1;
}

__global__ void deg_hist_kernel(const int* __restrict__ dst, int* deg, int E) {
    int e = blockIdx.x * blockDim.x + threadIdx.x;
    if (e < E) atomicAdd(&deg[dst[e]], 1);
}

__global__ void scan_block_sums(const int* __restrict__ deg, int* bsum, int nN) {
    __shared__ int sm[256];
    int i = blockIdx.x * 256 + threadIdx.x;
    sm[threadIdx.x] = (i < nN) ? deg[i] : 0;
    __syncthreads();
    for (int o = 128; o; o >>= 1) {
        if (threadIdx.x < o) sm[threadIdx.x] += sm[threadIdx.x + o];
        __syncthreads();
    }
    if (threadIdx.x == 0) bsum[blockIdx.x] = sm[0];
}

__global__ void scan_bsum_kernel(int* bsum, int nb) {
    __shared__ int sm[256];
    int t = threadIdx.x;
    int v = (t < nb) ? bsum[t] : 0;
    sm[t] = v;
    __syncthreads();
    for (int o = 1; o < 256; o <<= 1) {
        int add = (t >= o) ? sm[t - o] : 0;
        __syncthreads();
        sm[t] += add;
        __syncthreads();
    }
    if (t < nb) bsum[t] = sm[t] - v;
}

__global__ void scan_final_kernel(const int* __restrict__ deg, const int* __restrict__ bsum,
                                  int* rowptr, int* pos, int nN, int nEt) {
    __shared__ int sm[256];
    int t = threadIdx.x;
    int i = blockIdx.x * 256 + t;
    int v = (i < nN) ? deg[i] : 0;
    sm[t] = v;
    __syncthreads();
    for (int o = 1; o < 256; o <<= 1) {
        int add = (t >= o) ? sm[t - o] : 0;
        __syncthreads();
        sm[t] += add;
        __syncthreads();
    }
    if (i < nN) {
        int ex = sm[t] - v + bsum[blockIdx.x];
        rowptr[i] = ex;
        pos[i] = ex;
    }
    if (i == 0) rowptr[nN] = nEt;
}

__global__ void scatter_kernel(const int* __restrict__ src, const int* __restrict__ dst,
                               int* pos, int* eperm, int E, int nN) {
    int t = blockIdx.x * blockDim.x + threadIdx.x;
    if (t >= E + nN) return;
    int s, d;
    if (t < E) { s = src[t]; d = dst[t]; } else { s = d = t - E; }
    int p = atomicAdd(&pos[d], 1);
    eperm[p] = s;
}

// ---------------------------- TF32 helpers ----------------------------------
static __device__ __forceinline__ uint32_t f2tf32(float a) {
    uint32_t r;
    asm("cvt.rna.tf32.f32 %0, %1;" : "=r"(r) : "f"(a));
    return r;
}
static __device__ __forceinline__ void mma_tf32(float c[4], uint32_t a0, uint32_t a1,
                                                uint32_t a2, uint32_t a3,
                                                uint32_t b0, uint32_t b1) {
    asm volatile(
        "mma.sync.aligned.m16n8k8.row.col.f32.tf32.tf32.f32 "
        "{%0,%1,%2,%3}, {%4,%5,%6,%7}, {%8,%9}, {%0,%1,%2,%3};\n"
        : "+f"(c[0]), "+f"(c[1]), "+f"(c[2]), "+f"(c[3])
        : "r"(a0), "r"(a1), "r"(a2), "r"(a3), "r"(b0), "r"(b1));
}
static __device__ __forceinline__ void cpasync16(uint32_t dst, const void* src, int sz) {
    asm volatile("cp.async.cg.shared.global [%0], [%1], 16, %2;\n"
                 :: "r"(dst), "l"(src), "r"(sz));
}
static __device__ __forceinline__ void cpcommit() {
    asm volatile("cp.async.commit_group;\n");
}
template <int N>
static __device__ __forceinline__ void cpwait() {
    asm volatile("cp.async.wait_group %0;\n" :: "n"(N));
}

// -------------------- dual GEMM (xl and xr in one launch) --------------------
// C_half[M,Nc] = A[M,K] @ B_half[K,Nc] + bias_half.
// blockIdx.x in [0, 2*Nc/128): first half -> (Bl,bl,Cl), second -> (Br,br,Cr).
// BM=128 BN=128 BK=16, 256 threads, warp tile 64x32, mma m16n8k8 tf32,
// 3-product split for ~fp32 accuracy.
__global__ __launch_bounds__(256, 1) void gemm_dual_tf32_kernel(
    const float* __restrict__ A,
    const float* __restrict__ Bl, const float* __restrict__ Br,
    const float* __restrict__ bl, const float* __restrict__ br,
    float* __restrict__ Cl, float* __restrict__ Cr,
    int M, int K, int Nc) {
    __shared__ float As[2][128][20];
    __shared__ float Bs[2][16][136];

    const int tid = threadIdx.x;
    const int lane = tid & 31;
    const int warpId = tid >> 5;
    const int warpM = warpId & 1;     // 0..1 -> 64 rows each
    const int warpN = warpId >> 1;    // 0..3 -> 32 cols each
    const int r = lane >> 2;          // groupID
    const int c = lane & 3;           // threadID in group

    const int nb = Nc >> 7;           // col blocks per half
    const int half = blockIdx.x / nb;
    const int colLocal = (blockIdx.x - half * nb) * 128;
    const int rowBase = blockIdx.y * 128;
    const float* B = half ? Br : Bl;
    const float* bias = half ? br : bl;
    float* C = half ? Cr : Cl;

    float acc[4][4][4];
#pragma unroll
    for (int i = 0; i < 4; i++)
#pragma unroll
        for (int j = 0; j < 4; j++)
#pragma unroll
            for (int k = 0; k < 4; k++) acc[i][j][k] = 0.f;

    // decode load slots
    int arow[2], akq[2], bk[2], bnq[2];
#pragma unroll
    for (int j = 0; j < 2; j++) {
        int s = tid * 2 + j;
        arow[j] = s >> 2;  akq[j] = (s & 3) << 2;
        bk[j] = s >> 5;    bnq[j] = (s & 31) << 2;
    }

    const int T = K >> 4;

    auto issue_tile = [&](int t, int s) {
#pragma unroll
        for (int j = 0; j < 2; j++) {
            int gr = rowBase + arow[j];
            int grc = gr < M ? gr : (M - 1);
            const float* gp = A + (size_t)grc * K + t * 16 + akq[j];
            uint32_t sa = (uint32_t)__cvta_generic_to_shared(&As[s][arow[j]][akq[j]]);
            cpasync16(sa, gp, gr < M ? 16 : 0);
        }
#pragma unroll
        for (int j = 0; j < 2; j++) {
            const float* gp = B + (size_t)(t * 16 + bk[j]) * Nc + colLocal + bnq[j];
            uint32_t sa = (uint32_t)__cvta_generic_to_shared(&Bs[s][bk[j]][bnq[j]]);
            cpasync16(sa, gp, 16);
        }
        cpcommit();
    };

    issue_tile(0, 0);

    for (int t = 0; t < T; t++) {
        int s = t & 1;
        if (t + 1 < T) {
            issue_tile(t + 1, s ^ 1);
            cpwait<1>();
        } else {
            cpwait<0>();
        }
        __syncthreads();

#pragma unroll
        for (int kk = 0; kk < 16; kk += 8) {
            uint32_t Ahi[4][4], Alo[4][4], Bhi[4][2], Blo[4][2];
#pragma unroll
            for (int mt = 0; mt < 4; mt++) {
                int m = warpM * 64 + mt * 16 + r;
                float a0 = As[s][m][kk + c];
                float a1 = As[s][m + 8][kk + c];
                float a2 = As[s][m][kk + c + 4];
                float a3 = As[s][m + 8][kk + c + 4];
                Ahi[mt][0] = f2tf32(a0); Alo[mt][0] = f2tf32(a0 - __uint_as_float(Ahi[mt][0]));
                Ahi[mt][1] = f2tf32(a1); Alo[mt][1] = f2tf32(a1 - __uint_as_float(Ahi[mt][1]));
                Ahi[mt][2] = f2tf32(a2); Alo[mt][2] = f2tf32(a2 - __uint_as_float(Ahi[mt][2]));
                Ahi[mt][3] = f2tf32(a3); Alo[mt][3] = f2tf32(a3 - __uint_as_float(Ahi[mt][3]));
            }
#pragma unroll
            for (int nt = 0; nt < 4; nt++) {
                int n = warpN * 32 + nt * 8 + r;
                float b0 = Bs[s][kk + c][n];
                float b1 = Bs[s][kk + c + 4][n];
                Bhi[nt][0] = f2tf32(b0); Blo[nt][0] = f2tf32(b0 - __uint_as_float(Bhi[nt][0]));
                Bhi[nt][1] = f2tf32(b1); Blo[nt][1] = f2tf32(b1 - __uint_as_float(Bhi[nt][1]));
            }
#pragma unroll
            for (int mt = 0; mt < 4; mt++)
#pragma unroll
                for (int nt = 0; nt < 4; nt++) {
                    mma_tf32(acc[mt][nt], Alo[mt][0], Alo[mt][1], Alo[mt][2], Alo[mt][3],
                             Bhi[nt][0], Bhi[nt][1]);
                    mma_tf32(acc[mt][nt], Ahi[mt][0], Ahi[mt][1], Ahi[mt][2], Ahi[mt][3],
                             Blo[nt][0], Blo[nt][1]);
                    mma_tf32(acc[mt][nt], Ahi[mt][0], Ahi[mt][1], Ahi[mt][2], Ahi[mt][3],
                             Bhi[nt][0], Bhi[nt][1]);
                }
        }
        __syncthreads();
    }

    // store
#pragma unroll
    for (int mt = 0; mt < 4; mt++) {
        int row0 = rowBase + warpM * 64 + mt * 16 + r;
#pragma unroll
        for (int nt = 0; nt < 4; nt++) {
            int col = colLocal + warpN * 32 + nt * 8 + 2 * c;
            float b0 = bias[col], b1 = bias[col + 1];
            if (row0 < M) {
                float2 o = make_float2(acc[mt][nt][0] + b0, acc[mt][nt][1] + b1);
                *(float2*)&C[(size_t)row0 * Nc + col] = o;
            }
            if (row0 + 8 < M) {
                float2 o = make_float2(acc[mt][nt][2] + b0, acc[mt][nt][3] + b1);
                *(float2*)&C[(size_t)(row0 + 8) * Nc + col] = o;
            }
        }
    }
}

// --------------- fused GATv2 layer, online softmax (layers 1 & 2) -----------
// One warp per destination node.  Lane L: head h=L/4, sub=L%4, float4 cols
// f0+4c (f0 = 12h+sub, c=0..2).  Single pass over edges.
__global__ __launch_bounds__(256) void gat_fused_kernel(
    const float* __restrict__ xl, const float* __restrict__ xr,
    const float* __restrict__ att, const float* __restrict__ bias,
    const int* __restrict__ rowptr, const int* __restrict__ eperm,
    float* __restrict__ outFeat, int nN) {
    int warp = (blockIdx.x * blockDim.x + threadIdx.x) >> 5;
    if (warp >= nN) return;
    const int L = threadIdx.x & 31;
    const int sub = L & 3;
    const int f0 = 12 * (L >> 2) + sub;
    const int leader = L & ~3;

    const float4* xl4 = (const float4*)xl;
    const float4* xr4 = (const float4*)xr;
    const float4* att4 = (const float4*)att;
    const float4* bias4 = (const float4*)bias;

    float4 rxr[3], ratt[3];
#pragma unroll
    for (int cc = 0; cc < 3; cc++) {
        rxr[cc] = xr4[(size_t)warp * 96 + f0 + 4 * cc];
        ratt[cc] = att4[f0 + 4 * cc];
    }

    const int s0 = rowptr[warp];
    const int s1 = rowptr[warp + 1];

    float m = -FLT_MAX, d = 0.f;
    float4 acc[3];
#pragma unroll
    for (int cc = 0; cc < 3; cc++) acc[cc] = make_float4(0.f, 0.f, 0.f, 0.f);

    float4 nxt[3];
    {
        int sN = eperm[s0];
#pragma unroll
        for (int cc = 0; cc < 3; cc++) nxt[cc] = xl4[(size_t)sN * 96 + f0 + 4 * cc];
    }

    for (int e = s0; e < s1; e++) {
        float4 cur[3];
#pragma unroll
        for (int cc = 0; cc < 3; cc++) cur[cc] = nxt[cc];
        if (e + 1 < s1) {
            int sN = eperm[e + 1];
#pragma unroll
            for (int cc = 0; cc < 3; cc++) nxt[cc] = xl4[(size_t)sN * 96 + f0 + 4 * cc];
        }

        float p = 0.f;
#pragma unroll
        for (int cc = 0; cc < 3; cc++) {
            float4 a = cur[cc], rr = rxr[cc], w = ratt[cc];
            float v;
            v = a.x + rr.x; p += (v > 0.f ? v : NEG * v) * w.x;
            v = a.y + rr.y; p += (v > 0.f ? v : NEG * v) * w.y;
            v = a.z + rr.z; p += (v > 0.f ? v : NEG * v) * w.z;
            v = a.w + rr.w; p += (v > 0.f ? v : NEG * v) * w.w;
        }
        p += __shfl_down_sync(0xffffffffu, p, 2);
        p += __shfl_down_sync(0xffffffffu, p, 1);

        float scale, w;
        if (sub == 0) {
            float mn = fmaxf(m, p);
            scale = __expf(m - mn);
            w = __expf(p - mn);
            d = d * scale + w;
            m = mn;
        }
        scale = __shfl_sync(0xffffffffu, scale, leader);
        w = __shfl_sync(0xffffffffu, w, leader);

#pragma unroll
        for (int cc = 0; cc < 3; cc++) {
            acc[cc].x = acc[cc].x * scale + w * cur[cc].x;
            acc[cc].y = acc[cc].y * scale + w * cur[cc].y;
            acc[cc].z = acc[cc].z * scale + w * cur[cc].z;
            acc[cc].w = acc[cc].w * scale + w * cur[cc].w;
        }
    }

    float inv;
    if (sub == 0) inv = 1.f / (d + 1e-16f);
    inv = __shfl_sync(0xffffffffu, inv, leader);

#pragma unroll
    for (int cc = 0; cc < 3; cc++) {
        float4 b = bias4[f0 + 4 * cc];
        float4 o;
        o.x = acc[cc].x * inv + b.x; o.x = o.x > 0.f ? o.x : expm1f(o.x);
        o.y = acc[cc].y * inv + b.y; o.y = o.y > 0.f ? o.y : expm1f(o.y);
        o.z = acc[cc].z * inv + b.z; o.z = o.z > 0.f ? o.z : expm1f(o.z);
        o.w = acc[cc].w * inv + b.w; o.w = o.w > 0.f ? o.w : expm1f(o.w);
        ((float4*)outFeat)[(size_t)warp * 96 + f0 + 4 * cc] = o;
    }
}

// ------------------------- layer 3 ------------------------------------------
__global__ void l3_transform_kernel(const float* __restrict__ hfeat,
                                    const float* __restrict__ Wl, const float* __restrict__ bl,
                                    const float* __restrict__ Wr, const float* __restrict__ br,
                                    float* __restrict__ xl3, float* __restrict__ xr3,
                                    int nN) {
    int warp = (blockIdx.x * blockDim.x + threadIdx.x) >> 5;
    int lane = threadIdx.x & 31;
    if (warp >= nN) return;
    const float* row = hfeat + (size_t)warp * HID;
    float a0 = 0.f, a1 = 0.f, b0 = 0.f, b1 = 0.f;
#pragma unroll
    for (int k = lane; k < HID; k += 32) {
        float v = row[k];
        a0 += v * Wl[k * 2];
        a1 += v * Wl[k * 2 + 1];
        b0 += v * Wr[k * 2];
        b1 += v * Wr[k * 2 + 1];
    }
#pragma unroll
    for (int o = 16; o; o >>= 1) {
        a0 += __shfl_down_sync(0xffffffffu, a0, o);
        a1 += __shfl_down_sync(0xffffffffu, a1, o);
        b0 += __shfl_down_sync(0xffffffffu, b0, o);
        b1 += __shfl_down_sync(0xffffffffu, b1, o);
    }
    if (lane == 0) {
        xl3[warp * 2] = a0 + bl[0];
        xl3[warp * 2 + 1] = a1 + bl[1];
        xr3[warp * 2] = b0 + br[0];
        xr3[warp * 2 + 1] = b1 + br[1];
    }
}

__global__ void l3_fused_kernel(const float* __restrict__ xl3, const float* __restrict__ xr3,
                                const float* __restrict__ att3, const float* __restrict__ bias3,
                                const int* __restrict__ rowptr, const int* __restrict__ eperm,
                                float* __restrict__ out, int nN) {
    int warp = (blockIdx.x * blockDim.x + threadIdx.x) >> 5;
    if (warp >= nN) return;
    const int L = threadIdx.x & 31;
    const float xr0 = xr3[2 * warp], xr1 = xr3[2 * warp + 1];
    const float a0 = att3[0], a1 = att3[1];
    const int s0 = rowptr[warp], s1 = rowptr[warp + 1];

    float mx = -FLT_MAX;
    for (int e = s0 + L; e < s1; e += 32) {
        int s = eperm[e];
        float m0 = xl3[2 * s] + xr0;
        float m1 = xl3[2 * s + 1] + xr1;
        float sc = (m0 > 0.f ? m0 : NEG * m0) * a0 + (m1 > 0.f ? m1 : NEG * m1) * a1;
        mx = fmaxf(mx, sc);
    }
#pragma unroll
    for (int o = 16; o; o >>= 1) mx = fmaxf(mx, __shfl_xor_sync(0xffffffffu, mx, o));

    float den = 0.f, n0 = 0.f, n1 = 0.f;
    for (int e = s0 + L; e < s1; e += 32) {
        int s = eperm[e];
        float x0 = xl3[2 * s], x1 = xl3[2 * s + 1];
        float m0 = x0 + xr0, m1 = x1 + xr1;
        float sc = (m0 > 0.f ? m0 : NEG * m0) * a0 + (m1 > 0.f ? m1 : NEG * m1) * a1;
        float v = expf(sc - mx);
        den += v;
        n0 += v * x0;
        n1 += v * x1;
    }
#pragma unroll
    for (int o = 16; o; o >>= 1) {
        den += __shfl_xor_sync(0xffffffffu, den, o);
        n0 += __shfl_xor_sync(0xffffffffu, n0, o);
        n1 += __shfl_xor_sync(0xffffffffu, n1, o);
    }
    if (L == 0) {
        float id = 1.f / (den + 1e-16f);
        float z0 = n0 * id + bias3[0];
        float z1 = n1 * id + bias3[1];
        float m = fmaxf(z0, z1);
        float l = m + logf(expf(z0 - m) + expf(z1 - m));
        out[2 * warp] = z0 - l;
        out[2 * warp + 1] = z1 - l;
    }
}

// ------------------------------ host ----------------------------------------
extern "C" void kernel_launch(void* const* d_in, const int* in_sizes, int n_in,
                              void* d_out, int out_size) {
    const float* x     = (const float*)d_in[0];
    const int*   eidx  = (const int*)d_in[1];
    const float* Wl1   = (const float*)d_in[2];
    const float* bl1   = (const float*)d_in[3];
    const float* Wr1   = (const float*)d_in[4];
    const float* br1   = (const float*)d_in[5];
    const float* att1  = (const float*)d_in[6];
    const float* bias1 = (const float*)d_in[7];
    const float* Wl2   = (const float*)d_in[8];
    const float* bl2   = (const float*)d_in[9];
    const float* Wr2   = (const float*)d_in[10];
    const float* br2   = (const float*)d_in[11];
    const float* att2  = (const float*)d_in[12];
    const float* bias2 = (const float*)d_in[13];
    const float* Wl3   = (const float*)d_in[14];
    const float* bl3   = (const float*)d_in[15];
    const float* Wr3   = (const float*)d_in[16];
    const float* br3   = (const float*)d_in[17];
    const float* att3  = (const float*)d_in[18];
    const float* bias3 = (const float*)d_in[19];

    const int nN = in_sizes[0] / 128;
    const int nE = in_sizes[1] / 2;
    const int nEt = nE + nN;
    const int* srcArr = eidx;
    const int* dstArr = eidx + nE;

    float* xl;     cudaGetSymbolAddress((void**)&xl, g_xl);
    float* xr;     cudaGetSymbolAddress((void**)&xr, g_xr);
    float* feat;   cudaGetSymbolAddress((void**)&feat, g_feat);
    int* deg;      cudaGetSymbolAddress((void**)&deg, g_deg);
    int* rowptr;   cudaGetSymbolAddress((void**)&rowptr, g_rowptr);
    int* pos;      cudaGetSymbolAddress((void**)&pos, g_pos);
    int* eperm;    cudaGetSymbolAddress((void**)&eperm, g_eperm);
    int* bsum;     cudaGetSymbolAddress((void**)&bsum, g_bsum);
    float* xl3;    cudaGetSymbolAddress((void**)&xl3, g_xl3);
    float* xr3;    cudaGetSymbolAddress((void**)&xr3, g_xr3);

    const int nb = (nN + 255) / 256;

    // ----- CSR build (reused by all 3 layers) -----
    deg_init_kernel<<<nb, 256>>>(deg, nN);
    deg_hist_kernel<<<(nE + 255) / 256, 256>>>(dstArr, deg, nE);
    scan_block_sums<<<nb, 256>>>(deg, bsum, nN);
    scan_bsum_kernel<<<1, 256>>>(bsum, nb);
    scan_final_kernel<<<nb, 256>>>(deg, bsum, rowptr, pos, nN, nEt);
    scatter_kernel<<<(nEt + 255) / 256, 256>>>(srcArr, dstArr, pos, eperm, nE, nN);

    const dim3 gemmGrd(2 * (HID / 128), (nN + 127) / 128);   // 6 x 391
    const int fusedGrid = (nN + 7) / 8;

    // ----- layer 1 -----
    gemm_dual_tf32_kernel<<<gemmGrd, 256>>>(x, Wl1, Wr1, bl1, br1, xl, xr, nN, 128, HID);
    gat_fused_kernel<<<fusedGrid, 256>>>(xl, xr, att1, bias1, rowptr, eperm, feat, nN);

    // ----- layer 2 -----
    gemm_dual_tf32_kernel<<<gemmGrd, 256>>>(feat, Wl2, Wr2, bl2, br2, xl, xr, nN, HID, HID);
    gat_fused_kernel<<<fusedGrid, 256>>>(xl, xr, att2, bias2, rowptr, eperm, feat, nN);

    // ----- layer 3 -----
    l3_transform_kernel<<<(nN * 32 + 255) / 256, 256>>>(feat, Wl3, bl3, Wr3, br3,
                                                        xl3, xr3, nN);
    l3_fused_kernel<<<fusedGrid, 256>>>(xl3, xr3, att3, bias3, rowptr, eperm,
                                        (float*)d_out, nN);
}

// round 4
// speedup vs baseline: 6.2466x; 1.6921x over previous
#include <cuda_runtime.h>
#include <cstdint>
#include <cfloat>

// ---------------------------------------------------------------------------
// GATv2 3-layer forward.  CSR + online-softmax fused edges + 1xTF32 MMA.
// N=50000, E=500000 (+N self loops), F_IN=128, HID=384 (8 heads x 48), OUT=2.
// ---------------------------------------------------------------------------

#define NN_MAX 50000
#define EE_MAX 500000
#define ET_MAX (EE_MAX + NN_MAX)
#define HID 384
#define NHEAD 8
#define CH 48
#define NEG 0.2f

// ------------------------- scratch (device globals) ------------------------
__device__ float g_xl[NN_MAX * HID];
__device__ float g_xr[NN_MAX * HID];
__device__ float g_feat[NN_MAX * HID];
__device__ int   g_deg[NN_MAX];
__device__ int   g_rowptr[NN_MAX + 1];
__device__ int   g_pos[NN_MAX];
__device__ int   g_eperm[ET_MAX];
__device__ int   g_bsum[256];
__device__ float g_xl3[NN_MAX * 2];
__device__ float g_xr3[NN_MAX * 2];

// ------------------------------ CSR build -----------------------------------
__global__ void deg_init_kernel(int* deg, int nN) {
    int i = blockIdx.x * blockDim.x + threadIdx.x;
    if (i < nN) deg[i] = 1;
}

__global__ void deg_hist_kernel(const int* __restrict__ dst, int* deg, int E) {
    int e = blockIdx.x * blockDim.x + threadIdx.x;
    if (e < E) atomicAdd(&deg[dst[e]], 1);
}

__global__ void scan_block_sums(const int* __restrict__ deg, int* bsum, int nN) {
    __shared__ int sm[256];
    int i = blockIdx.x * 256 + threadIdx.x;
    sm[threadIdx.x] = (i < nN) ? deg[i] : 0;
    __syncthreads();
    for (int o = 128; o; o >>= 1) {
        if (threadIdx.x < o) sm[threadIdx.x] += sm[threadIdx.x + o];
        __syncthreads();
    }
    if (threadIdx.x == 0) bsum[blockIdx.x] = sm[0];
}

__global__ void scan_bsum_kernel(int* bsum, int nb) {
    __shared__ int sm[256];
    int t = threadIdx.x;
    int v = (t < nb) ? bsum[t] : 0;
    sm[t] = v;
    __syncthreads();
    for (int o = 1; o < 256; o <<= 1) {
        int add = (t >= o) ? sm[t - o] : 0;
        __syncthreads();
        sm[t] += add;
        __syncthreads();
    }
    if (t < nb) bsum[t] = sm[t] - v;
}

__global__ void scan_final_kernel(const int* __restrict__ deg, const int* __restrict__ bsum,
                                  int* rowptr, int* pos, int nN, int nEt) {
    __shared__ int sm[256];
    int t = threadIdx.x;
    int i = blockIdx.x * 256 + t;
    int v = (i < nN) ? deg[i] : 0;
    sm[t] = v;
    __syncthreads();
    for (int o = 1; o < 256; o <<= 1) {
        int add = (t >= o) ? sm[t - o] : 0;
        __syncthreads();
        sm[t] += add;
        __syncthreads();
    }
    if (i < nN) {
        int ex = sm[t] - v + bsum[blockIdx.x];
        rowptr[i] = ex;
        pos[i] = ex;
    }
    if (i == 0) rowptr[nN] = nEt;
}

__global__ void scatter_kernel(const int* __restrict__ src, const int* __restrict__ dst,
                               int* pos, int* eperm, int E, int nN) {
    int t = blockIdx.x * blockDim.x + threadIdx.x;
    if (t >= E + nN) return;
    int s, d;
    if (t < E) { s = src[t]; d = dst[t]; } else { s = d = t - E; }
    int p = atomicAdd(&pos[d], 1);
    eperm[p] = s;
}

// ---------------------------- TF32 helpers ----------------------------------
static __device__ __forceinline__ uint32_t f2tf32(float a) {
    uint32_t r;
    asm("cvt.rna.tf32.f32 %0, %1;" : "=r"(r) : "f"(a));
    return r;
}
static __device__ __forceinline__ void mma_tf32(float c[4], uint32_t a0, uint32_t a1,
                                                uint32_t a2, uint32_t a3,
                                                uint32_t b0, uint32_t b1) {
    asm volatile(
        "mma.sync.aligned.m16n8k8.row.col.f32.tf32.tf32.f32 "
        "{%0,%1,%2,%3}, {%4,%5,%6,%7}, {%8,%9}, {%0,%1,%2,%3};\n"
        : "+f"(c[0]), "+f"(c[1]), "+f"(c[2]), "+f"(c[3])
        : "r"(a0), "r"(a1), "r"(a2), "r"(a3), "r"(b0), "r"(b1));
}
static __device__ __forceinline__ void cpasync16(uint32_t dst, const void* src, int sz) {
    asm volatile("cp.async.cg.shared.global [%0], [%1], 16, %2;\n"
                 :: "r"(dst), "l"(src), "r"(sz));
}
static __device__ __forceinline__ void cpcommit() {
    asm volatile("cp.async.commit_group;\n");
}
template <int N>
static __device__ __forceinline__ void cpwait() {
    asm volatile("cp.async.wait_group %0;\n" :: "n"(N));
}

// -------------------- dual GEMM (xl and xr in one launch) --------------------
// C_half[M,Nc] = A[M,K] @ B_half[K,Nc] + bias_half.
// blockIdx.x in [0, 2*Nc/128): first half -> (Bl,bl,Cl), second -> (Br,br,Cr).
// BM=128 BN=128 BK=16, 256 threads, warp tile 64x32, mma m16n8k8 1xTF32.
__global__ __launch_bounds__(256, 2) void gemm_dual_tf32_kernel(
    const float* __restrict__ A,
    const float* __restrict__ Bl, const float* __restrict__ Br,
    const float* __restrict__ bl, const float* __restrict__ br,
    float* __restrict__ Cl, float* __restrict__ Cr,
    int M, int K, int Nc) {
    __shared__ float As[2][128][20];
    __shared__ float Bs[2][16][136];

    const int tid = threadIdx.x;
    const int lane = tid & 31;
    const int warpId = tid >> 5;
    const int warpM = warpId & 1;     // 0..1 -> 64 rows each
    const int warpN = warpId >> 1;    // 0..3 -> 32 cols each
    const int r = lane >> 2;          // groupID
    const int c = lane & 3;           // threadID in group

    const int nb = Nc >> 7;           // col blocks per half
    const int half = blockIdx.x / nb;
    const int colLocal = (blockIdx.x - half * nb) * 128;
    const int rowBase = blockIdx.y * 128;
    const float* B = half ? Br : Bl;
    const float* bias = half ? br : bl;
    float* C = half ? Cr : Cl;

    float acc[4][4][4];
#pragma unroll
    for (int i = 0; i < 4; i++)
#pragma unroll
        for (int j = 0; j < 4; j++)
#pragma unroll
            for (int k = 0; k < 4; k++) acc[i][j][k] = 0.f;

    // decode load slots
    int arow[2], akq[2], bk[2], bnq[2];
#pragma unroll
    for (int j = 0; j < 2; j++) {
        int s = tid * 2 + j;
        arow[j] = s >> 2;  akq[j] = (s & 3) << 2;
        bk[j] = s >> 5;    bnq[j] = (s & 31) << 2;
    }

    const int T = K >> 4;

    auto issue_tile = [&](int t, int s) {
#pragma unroll
        for (int j = 0; j < 2; j++) {
            int gr = rowBase + arow[j];
            int grc = gr < M ? gr : (M - 1);
            const float* gp = A + (size_t)grc * K + t * 16 + akq[j];
            uint32_t sa = (uint32_t)__cvta_generic_to_shared(&As[s][arow[j]][akq[j]]);
            cpasync16(sa, gp, gr < M ? 16 : 0);
        }
#pragma unroll
        for (int j = 0; j < 2; j++) {
            const float* gp = B + (size_t)(t * 16 + bk[j]) * Nc + colLocal + bnq[j];
            uint32_t sa = (uint32_t)__cvta_generic_to_shared(&Bs[s][bk[j]][bnq[j]]);
            cpasync16(sa, gp, 16);
        }
        cpcommit();
    };

    issue_tile(0, 0);

    for (int t = 0; t < T; t++) {
        int s = t & 1;
        if (t + 1 < T) {
            issue_tile(t + 1, s ^ 1);
            cpwait<1>();
        } else {
            cpwait<0>();
        }
        __syncthreads();

#pragma unroll
        for (int kk = 0; kk < 16; kk += 8) {
            uint32_t Ah[4][4], Bh[4][2];
#pragma unroll
            for (int mt = 0; mt < 4; mt++) {
                int m = warpM * 64 + mt * 16 + r;
                Ah[mt][0] = f2tf32(As[s][m][kk + c]);
                Ah[mt][1] = f2tf32(As[s][m + 8][kk + c]);
                Ah[mt][2] = f2tf32(As[s][m][kk + c + 4]);
                Ah[mt][3] = f2tf32(As[s][m + 8][kk + c + 4]);
            }
#pragma unroll
            for (int nt = 0; nt < 4; nt++) {
                int n = warpN * 32 + nt * 8 + r;
                Bh[nt][0] = f2tf32(Bs[s][kk + c][n]);
                Bh[nt][1] = f2tf32(Bs[s][kk + c + 4][n]);
            }
#pragma unroll
            for (int mt = 0; mt < 4; mt++)
#pragma unroll
                for (int nt = 0; nt < 4; nt++) {
                    mma_tf32(acc[mt][nt], Ah[mt][0], Ah[mt][1], Ah[mt][2], Ah[mt][3],
                             Bh[nt][0], Bh[nt][1]);
                }
        }
        __syncthreads();
    }

    // store
#pragma unroll
    for (int mt = 0; mt < 4; mt++) {
        int row0 = rowBase + warpM * 64 + mt * 16 + r;
#pragma unroll
        for (int nt = 0; nt < 4; nt++) {
            int col = colLocal + warpN * 32 + nt * 8 + 2 * c;
            float b0 = bias[col], b1 = bias[col + 1];
            if (row0 < M) {
                float2 o = make_float2(acc[mt][nt][0] + b0, acc[mt][nt][1] + b1);
                *(float2*)&C[(size_t)row0 * Nc + col] = o;
            }
            if (row0 + 8 < M) {
                float2 o = make_float2(acc[mt][nt][2] + b0, acc[mt][nt][3] + b1);
                *(float2*)&C[(size_t)(row0 + 8) * Nc + col] = o;
            }
        }
    }
}

// --------------- fused GATv2 layer, online softmax (layers 1 & 2) -----------
// One warp per destination node.  Lane L: head h=L/4, sub=L%4, float4 cols
// f0+4c (f0 = 12h+sub, c=0..2).  Single pass over edges.
__global__ __launch_bounds__(256) void gat_fused_kernel(
    const float* __restrict__ xl, const float* __restrict__ xr,
    const float* __restrict__ att, const float* __restrict__ bias,
    const int* __restrict__ rowptr, const int* __restrict__ eperm,
    float* __restrict__ outFeat, int nN) {
    int warp = (blockIdx.x * blockDim.x + threadIdx.x) >> 5;
    if (warp >= nN) return;
    const int L = threadIdx.x & 31;
    const int sub = L & 3;
    const int f0 = 12 * (L >> 2) + sub;
    const int leader = L & ~3;

    const float4* xl4 = (const float4*)xl;
    const float4* xr4 = (const float4*)xr;
    const float4* att4 = (const float4*)att;
    const float4* bias4 = (const float4*)bias;

    float4 rxr[3], ratt[3];
#pragma unroll
    for (int cc = 0; cc < 3; cc++) {
        rxr[cc] = xr4[(size_t)warp * 96 + f0 + 4 * cc];
        ratt[cc] = att4[f0 + 4 * cc];
    }

    const int s0 = rowptr[warp];
    const int s1 = rowptr[warp + 1];

    float m = -FLT_MAX, d = 0.f;
    float4 acc[3];
#pragma unroll
    for (int cc = 0; cc < 3; cc++) acc[cc] = make_float4(0.f, 0.f, 0.f, 0.f);

    float4 nxt[3];
    {
        int sN = eperm[s0];
#pragma unroll
        for (int cc = 0; cc < 3; cc++) nxt[cc] = xl4[(size_t)sN * 96 + f0 + 4 * cc];
    }

    for (int e = s0; e < s1; e++) {
        float4 cur[3];
#pragma unroll
        for (int cc = 0; cc < 3; cc++) cur[cc] = nxt[cc];
        if (e + 1 < s1) {
            int sN = eperm[e + 1];
#pragma unroll
            for (int cc = 0; cc < 3; cc++) nxt[cc] = xl4[(size_t)sN * 96 + f0 + 4 * cc];
        }

        float p = 0.f;
#pragma unroll
        for (int cc = 0; cc < 3; cc++) {
            float4 a = cur[cc], rr = rxr[cc], w = ratt[cc];
            float v;
            v = a.x + rr.x; p += (v > 0.f ? v : NEG * v) * w.x;
            v = a.y + rr.y; p += (v > 0.f ? v : NEG * v) * w.y;
            v = a.z + rr.z; p += (v > 0.f ? v : NEG * v) * w.z;
            v = a.w + rr.w; p += (v > 0.f ? v : NEG * v) * w.w;
        }
        p += __shfl_down_sync(0xffffffffu, p, 2);
        p += __shfl_down_sync(0xffffffffu, p, 1);

        float scale, w;
        if (sub == 0) {
            float mn = fmaxf(m, p);
            scale = __expf(m - mn);
            w = __expf(p - mn);
            d = d * scale + w;
            m = mn;
        }
        scale = __shfl_sync(0xffffffffu, scale, leader);
        w = __shfl_sync(0xffffffffu, w, leader);

#pragma unroll
        for (int cc = 0; cc < 3; cc++) {
            acc[cc].x = acc[cc].x * scale + w * cur[cc].x;
            acc[cc].y = acc[cc].y * scale + w * cur[cc].y;
            acc[cc].z = acc[cc].z * scale + w * cur[cc].z;
            acc[cc].w = acc[cc].w * scale + w * cur[cc].w;
        }
    }

    float inv;
    if (sub == 0) inv = 1.f / (d + 1e-16f);
    inv = __shfl_sync(0xffffffffu, inv, leader);

#pragma unroll
    for (int cc = 0; cc < 3; cc++) {
        float4 b = bias4[f0 + 4 * cc];
        float4 o;
        o.x = acc[cc].x * inv + b.x; o.x = o.x > 0.f ? o.x : expm1f(o.x);
        o.y = acc[cc].y * inv + b.y; o.y = o.y > 0.f ? o.y : expm1f(o.y);
        o.z = acc[cc].z * inv + b.z; o.z = o.z > 0.f ? o.z : expm1f(o.z);
        o.w = acc[cc].w * inv + b.w; o.w = o.w > 0.f ? o.w : expm1f(o.w);
        ((float4*)outFeat)[(size_t)warp * 96 + f0 + 4 * cc] = o;
    }
}

// ------------------------- layer 3 ------------------------------------------
__global__ void l3_transform_kernel(const float* __restrict__ hfeat,
                                    const float* __restrict__ Wl, const float* __restrict__ bl,
                                    const float* __restrict__ Wr, const float* __restrict__ br,
                                    float* __restrict__ xl3, float* __restrict__ xr3,
                                    int nN) {
    int warp = (blockIdx.x * blockDim.x + threadIdx.x) >> 5;
    int lane = threadIdx.x & 31;
    if (warp >= nN) return;
    const float* row = hfeat + (size_t)warp * HID;
    float a0 = 0.f, a1 = 0.f, b0 = 0.f, b1 = 0.f;
#pragma unroll
    for (int k = lane; k < HID; k += 32) {
        float v = row[k];
        a0 += v * Wl[k * 2];
        a1 += v * Wl[k * 2 + 1];
        b0 += v * Wr[k * 2];
        b1 += v * Wr[k * 2 + 1];
    }
#pragma unroll
    for (int o = 16; o; o >>= 1) {
        a0 += __shfl_down_sync(0xffffffffu, a0, o);
        a1 += __shfl_down_sync(0xffffffffu, a1, o);
        b0 += __shfl_down_sync(0xffffffffu, b0, o);
        b1 += __shfl_down_sync(0xffffffffu, b1, o);
    }
    if (lane == 0) {
        xl3[warp * 2] = a0 + bl[0];
        xl3[warp * 2 + 1] = a1 + bl[1];
        xr3[warp * 2] = b0 + br[0];
        xr3[warp * 2 + 1] = b1 + br[1];
    }
}

__global__ void l3_fused_kernel(const float* __restrict__ xl3, const float* __restrict__ xr3,
                                const float* __restrict__ att3, const float* __restrict__ bias3,
                                const int* __restrict__ rowptr, const int* __restrict__ eperm,
                                float* __restrict__ out, int nN) {
    int warp = (blockIdx.x * blockDim.x + threadIdx.x) >> 5;
    if (warp >= nN) return;
    const int L = threadIdx.x & 31;
    const float xr0 = xr3[2 * warp], xr1 = xr3[2 * warp + 1];
    const float a0 = att3[0], a1 = att3[1];
    const int s0 = rowptr[warp], s1 = rowptr[warp + 1];

    float mx = -FLT_MAX;
    for (int e = s0 + L; e < s1; e += 32) {
        int s = eperm[e];
        float m0 = xl3[2 * s] + xr0;
        float m1 = xl3[2 * s + 1] + xr1;
        float sc = (m0 > 0.f ? m0 : NEG * m0) * a0 + (m1 > 0.f ? m1 : NEG * m1) * a1;
        mx = fmaxf(mx, sc);
    }
#pragma unroll
    for (int o = 16; o; o >>= 1) mx = fmaxf(mx, __shfl_xor_sync(0xffffffffu, mx, o));

    float den = 0.f, n0 = 0.f, n1 = 0.f;
    for (int e = s0 + L; e < s1; e += 32) {
        int s = eperm[e];
        float x0 = xl3[2 * s], x1 = xl3[2 * s + 1];
        float m0 = x0 + xr0, m1 = x1 + xr1;
        float sc = (m0 > 0.f ? m0 : NEG * m0) * a0 + (m1 > 0.f ? m1 : NEG * m1) * a1;
        float v = expf(sc - mx);
        den += v;
        n0 += v * x0;
        n1 += v * x1;
    }
#pragma unroll
    for (int o = 16; o; o >>= 1) {
        den += __shfl_xor_sync(0xffffffffu, den, o);
        n0 += __shfl_xor_sync(0xffffffffu, n0, o);
        n1 += __shfl_xor_sync(0xffffffffu, n1, o);
    }
    if (L == 0) {
        float id = 1.f / (den + 1e-16f);
        float z0 = n0 * id + bias3[0];
        float z1 = n1 * id + bias3[1];
        float m = fmaxf(z0, z1);
        float l = m + logf(expf(z0 - m) + expf(z1 - m));
        out[2 * warp] = z0 - l;
        out[2 * warp + 1] = z1 - l;
    }
}

// ------------------------------ host ----------------------------------------
extern "C" void kernel_launch(void* const* d_in, const int* in_sizes, int n_in,
                              void* d_out, int out_size) {
    const float* x     = (const float*)d_in[0];
    const int*   eidx  = (const int*)d_in[1];
    const float* Wl1   = (const float*)d_in[2];
    const float* bl1   = (const float*)d_in[3];
    const float* Wr1   = (const float*)d_in[4];
    const float* br1   = (const float*)d_in[5];
    const float* att1  = (const float*)d_in[6];
    const float* bias1 = (const float*)d_in[7];
    const float* Wl2   = (const float*)d_in[8];
    const float* bl2   = (const float*)d_in[9];
    const float* Wr2   = (const float*)d_in[10];
    const float* br2   = (const float*)d_in[11];
    const float* att2  = (const float*)d_in[12];
    const float* bias2 = (const float*)d_in[13];
    const float* Wl3   = (const float*)d_in[14];
    const float* bl3   = (const float*)d_in[15];
    const float* Wr3   = (const float*)d_in[16];
    const float* br3   = (const float*)d_in[17];
    const float* att3  = (const float*)d_in[18];
    const float* bias3 = (const float*)d_in[19];

    const int nN = in_sizes[0] / 128;
    const int nE = in_sizes[1] / 2;
    const int nEt = nE + nN;
    const int* srcArr = eidx;
    const int* dstArr = eidx + nE;

    float* xl;     cudaGetSymbolAddress((void**)&xl, g_xl);
    float* xr;     cudaGetSymbolAddress((void**)&xr, g_xr);
    float* feat;   cudaGetSymbolAddress((void**)&feat, g_feat);
    int* deg;      cudaGetSymbolAddress((void**)&deg, g_deg);
    int* rowptr;   cudaGetSymbolAddress((void**)&rowptr, g_rowptr);
    int* pos;      cudaGetSymbolAddress((void**)&pos, g_pos);
    int* eperm;    cudaGetSymbolAddress((void**)&eperm, g_eperm);
    int* bsum;     cudaGetSymbolAddress((void**)&bsum, g_bsum);
    float* xl3;    cudaGetSymbolAddress((void**)&xl3, g_xl3);
    float* xr3;    cudaGetSymbolAddress((void**)&xr3, g_xr3);

    const int nb = (nN + 255) / 256;

    // ----- CSR build (reused by all 3 layers) -----
    deg_init_kernel<<<nb, 256>>>(deg, nN);
    deg_hist_kernel<<<(nE + 255) / 256, 256>>>(dstArr, deg, nE);
    scan_block_sums<<<nb, 256>>>(deg, bsum, nN);
    scan_bsum_kernel<<<1, 256>>>(bsum, nb);
    scan_final_kernel<<<nb, 256>>>(deg, bsum, rowptr, pos, nN, nEt);
    scatter_kernel<<<(nEt + 255) / 256, 256>>>(srcArr, dstArr, pos, eperm, nE, nN);

    const dim3 gemmGrd(2 * (HID / 128), (nN + 127) / 128);   // 6 x 391
    const int fusedGrid = (nN + 7) / 8;

    // ----- layer 1 -----
    gemm_dual_tf32_kernel<<<gemmGrd, 256>>>(x, Wl1, Wr1, bl1, br1, xl, xr, nN, 128, HID);
    gat_fused_kernel<<<fusedGrid, 256>>>(xl, xr, att1, bias1, rowptr, eperm, feat, nN);

    // ----- layer 2 -----
    gemm_dual_tf32_kernel<<<gemmGrd, 256>>>(feat, Wl2, Wr2, bl2, br2, xl, xr, nN, HID, HID);
    gat_fused_kernel<<<fusedGrid, 256>>>(xl, xr, att2, bias2, rowptr, eperm, feat, nN);

    // ----- layer 3 -----
    l3_transform_kernel<<<(nN * 32 + 255) / 256, 256>>>(feat, Wl3, bl3, Wr3, br3,
                                                        xl3, xr3, nN);
    l3_fused_kernel<<<fusedGrid, 256>>>(xl3, xr3, att3, bias3, rowptr, eperm,
                                        (float*)d_out, nN);
}